// round 1
// baseline (speedup 1.0000x reference)
#include <cuda_runtime.h>

#define DEV_INLINE __device__ __forceinline__

constexpr int B  = 64;
constexpr int C  = 2048;
constexpr int P  = 196;     // H*W
constexpr int PP = 224;     // padded P (7 warps * 32)
constexpr int KK = 512;     // hidden k
constexpr int HS = 1024;

// ---- scratch (static device globals; no allocation allowed) ----
static __device__ float g_ic[B * C];
static __device__ float g_bcu[B * KK];
static __device__ float g_bsu[B * KK];
static __device__ float g_sc[B * C];
static __device__ float g_ac[B * C];
static __device__ float g_xw[(size_t)B * C * PP];   // padded channel-weighted features
static __device__ float g_ssq[B * PP];
static __device__ float g_inv[B * PP];
static __device__ float g_ss[B * P];
static __device__ float g_asp[B * P];

DEV_INLINE float tanh_fast(float x) {
    float y;
    asm("tanh.approx.f32 %0, %1;" : "=f"(y) : "f"(x));
    return y;
}

// ---- K0: zero accumulators (must happen every call: graph is replayed) ----
__global__ void k0_zero() {
    int i = blockIdx.x * 256 + threadIdx.x;
    if (i < B * PP) g_ssq[i] = 0.f;
    if (i < B * P)  g_ss[i]  = 0.f;
}

// ---- K1: per-(b,c) sum & sumsq over P -> ic = sum / (P * max(norm, eps)) ----
__global__ void k1_stats(const float* __restrict__ x) {
    int warp = (blockIdx.x * blockDim.x + threadIdx.x) >> 5;
    int lane = threadIdx.x & 31;
    if (warp >= B * C) return;
    const float4* row = (const float4*)(x + (size_t)warp * P);
    float s = 0.f, sq = 0.f;
    for (int v = lane; v < 49; v += 32) {
        float4 f = row[v];
        s  += f.x + f.y + f.z + f.w;
        sq += f.x * f.x + f.y * f.y + f.z * f.z + f.w * f.w;
    }
    #pragma unroll
    for (int o = 16; o; o >>= 1) {
        s  += __shfl_down_sync(0xffffffffu, s,  o);
        sq += __shfl_down_sync(0xffffffffu, sq, o);
    }
    if (lane == 0) {
        float n = sqrtf(sq);
        g_ic[warp] = s / (196.f * fmaxf(n, 1e-12f));
    }
}

// ---- K2: uc = whc@h, us = whs@h; fold in bc/bs ----
__global__ void k2_proj(const float* __restrict__ h, const float* __restrict__ whc,
                        const float* __restrict__ whs, const float* __restrict__ bc,
                        const float* __restrict__ bs) {
    int b = blockIdx.x;
    int j = threadIdx.x;  // 512 threads
    __shared__ float hsm[HS];
    for (int i = threadIdx.x; i < HS; i += KK) hsm[i] = h[b * HS + i];
    __syncthreads();
    const float* rc = whc + (size_t)j * HS;
    const float* rs = whs + (size_t)j * HS;
    float a = 0.f, d = 0.f;
    #pragma unroll 4
    for (int i = 0; i < HS; i++) {
        a = fmaf(rc[i], hsm[i], a);
        d = fmaf(rs[i], hsm[i], d);
    }
    g_bcu[b * KK + j] = a + bc[j];
    g_bsu[b * KK + j] = d + bs[j];
}

// ---- K3: sc[b,c] = sum_j wci[j]*tanh(wc[j]*ic + bcu[b,j])  (bci dropped: softmax-invariant)
__global__ void k3_sc(const float* __restrict__ wc, const float* __restrict__ wci) {
    int b = blockIdx.y;
    int c = blockIdx.x * 256 + threadIdx.x;
    __shared__ float swc[KK], swi[KK], sbu[KK];
    for (int i = threadIdx.x; i < KK; i += 256) {
        swc[i] = wc[i];
        swi[i] = wci[i];
        sbu[i] = g_bcu[b * KK + i];
    }
    __syncthreads();
    float icv = g_ic[b * C + c];
    float acc = 0.f;
    #pragma unroll 8
    for (int j = 0; j < KK; j++)
        acc = fmaf(swi[j], tanh_fast(fmaf(swc[j], icv, sbu[j])), acc);
    g_sc[b * C + c] = acc;
}

// ---- K4: softmax over C per batch ----
__global__ void k4_softmax_c() {
    int b = blockIdx.x, t = threadIdx.x;  // 256 threads
    __shared__ float red[256];
    float vals[8];
    float m = -1e30f;
    #pragma unroll
    for (int i = 0; i < 8; i++) {
        vals[i] = g_sc[b * C + t + 256 * i];
        m = fmaxf(m, vals[i]);
    }
    red[t] = m; __syncthreads();
    for (int o = 128; o; o >>= 1) { if (t < o) red[t] = fmaxf(red[t], red[t + o]); __syncthreads(); }
    m = red[0]; __syncthreads();
    float s = 0.f;
    #pragma unroll
    for (int i = 0; i < 8; i++) { vals[i] = __expf(vals[i] - m); s += vals[i]; }
    red[t] = s; __syncthreads();
    for (int o = 128; o; o >>= 1) { if (t < o) red[t] += red[t + o]; __syncthreads(); }
    float inv = 1.f / red[0];
    #pragma unroll
    for (int i = 0; i < 8; i++) g_ac[b * C + t + 256 * i] = vals[i] * inv;
}

// ---- K5: xw = x*ac (padded to PP, zero pad); accumulate per-(b,p) sumsq ----
__global__ void k5_xw(const float* __restrict__ x) {
    int b = blockIdx.y;
    int cbase = blockIdx.x * 128;
    int w = threadIdx.x >> 5, lane = threadIdx.x & 31;
    float sq[7] = {0.f, 0.f, 0.f, 0.f, 0.f, 0.f, 0.f};
    for (int it = 0; it < 16; it++) {
        int c = cbase + w * 16 + it;
        float a = g_ac[b * C + c];
        const float* xr = x + ((size_t)b * C + c) * P;
        float* xwr = g_xw + ((size_t)b * C + c) * PP;
        #pragma unroll
        for (int i = 0; i < 7; i++) {
            int p = lane + 32 * i;
            float v = (p < P) ? xr[p] * a : 0.f;
            xwr[p] = v;
            sq[i] += v * v;
        }
    }
    #pragma unroll
    for (int i = 0; i < 7; i++) {
        int p = lane + 32 * i;
        if (p < P) atomicAdd(&g_ssq[b * PP + p], sq[i]);
    }
}

// ---- K6: inv spatial norms ----
__global__ void k6_inv() {
    int i = blockIdx.x * 256 + threadIdx.x;
    if (i < B * PP) {
        float n = sqrtf(g_ssq[i]);
        g_inv[i] = 1.f / fmaxf(n, 1e-12f);
    }
}

// ---- K7: fused spatial GEMM + tanh + wsi-reduction -> ss[b,p] ----
// block: (jbase tile of 64 j) x (batch b); 256 threads = 8 warps,
// warp w owns j = jbase + w*8 .. +8, lanes own p = lane + 32*i (i<7).
__global__ void __launch_bounds__(256) k7_ss(const float* __restrict__ ws,
                                             const float* __restrict__ wsi) {
    int b = blockIdx.y;
    int jbase = blockIdx.x * 64;
    int w = threadIdx.x >> 5, lane = threadIdx.x & 31;
    __shared__ float sx[32][PP];   // 28 KB
    __shared__ float sw[64][32];   //  8 KB
    float acc[8][7];
    #pragma unroll
    for (int t = 0; t < 8; t++)
        #pragma unroll
        for (int i = 0; i < 7; i++) acc[t][i] = 0.f;

    const float4* xw4 = (const float4*)(g_xw + (size_t)b * C * PP);
    const float4* ws4 = (const float4*)ws;

    for (int c0 = 0; c0 < C; c0 += 32) {
        __syncthreads();
        // stage x chunk [32 x 224] = 1792 float4
        #pragma unroll
        for (int r = 0; r < 7; r++) {
            int idx = threadIdx.x + 256 * r;
            int cc = idx / 56, q = idx % 56;
            float4 f = xw4[(size_t)(c0 + cc) * 56 + q];
            *(float4*)&sx[cc][4 * q] = f;
        }
        // stage ws chunk [64 x 32] = 512 float4
        #pragma unroll
        for (int r = 0; r < 2; r++) {
            int idx = threadIdx.x + 256 * r;
            int jj = idx >> 3, q = idx & 7;
            float4 f = ws4[(size_t)(jbase + jj) * 512 + (c0 >> 2) + q];
            *(float4*)&sw[jj][4 * q] = f;
        }
        __syncthreads();
        #pragma unroll
        for (int cc = 0; cc < 32; cc++) {
            float xv[7];
            #pragma unroll
            for (int i = 0; i < 7; i++) xv[i] = sx[cc][lane + 32 * i];
            #pragma unroll
            for (int t = 0; t < 8; t++) {
                float wv = sw[w * 8 + t][cc];
                #pragma unroll
                for (int i = 0; i < 7; i++) acc[t][i] = fmaf(wv, xv[i], acc[t][i]);
            }
        }
    }

    // epilogue: per-p inv-norm, bias, tanh, weighted j-reduction
    float part[7], invp[7];
    #pragma unroll
    for (int i = 0; i < 7; i++) {
        part[i] = 0.f;
        invp[i] = g_inv[b * PP + lane + 32 * i];
    }
    #pragma unroll
    for (int t = 0; t < 8; t++) {
        int j = jbase + w * 8 + t;
        float bj = g_bsu[b * KK + j];
        float wi = wsi[j];
        #pragma unroll
        for (int i = 0; i < 7; i++) {
            float g = fmaf(acc[t][i], invp[i], bj);
            part[i] = fmaf(wi, tanh_fast(g), part[i]);
        }
    }
    #pragma unroll
    for (int i = 0; i < 7; i++) {
        int p = lane + 32 * i;
        if (p < P) atomicAdd(&g_ss[b * P + p], part[i]);
    }
}

// ---- K8: softmax over P per batch ----
__global__ void k8_softmax_p() {
    int b = blockIdx.x, t = threadIdx.x;  // 256 threads
    __shared__ float red[256];
    float v = (t < P) ? g_ss[b * P + t] : -1e30f;
    red[t] = v; __syncthreads();
    for (int o = 128; o; o >>= 1) { if (t < o) red[t] = fmaxf(red[t], red[t + o]); __syncthreads(); }
    float m = red[0]; __syncthreads();
    float e = (t < P) ? __expf(v - m) : 0.f;
    red[t] = e; __syncthreads();
    for (int o = 128; o; o >>= 1) { if (t < o) red[t] += red[t + o]; __syncthreads(); }
    if (t < P) g_asp[b * P + t] = e / red[0];
}

// ---- K9: out = xw * asp (de-pad), float4 ----
__global__ void k9_out(float* __restrict__ out) {
    int idx = blockIdx.x * 256 + threadIdx.x;  // over B*C*49 float4s
    if (idx >= B * C * 49) return;
    int q = idx % 49;
    int bc = idx / 49;
    int b = bc / C;
    float4 xv = *(const float4*)(g_xw + (size_t)bc * PP + 4 * q);
    float4 av = *(const float4*)(g_asp + b * P + 4 * q);
    float4 o;
    o.x = xv.x * av.x; o.y = xv.y * av.y; o.z = xv.z * av.z; o.w = xv.w * av.w;
    ((float4*)out)[idx] = o;
}

extern "C" void kernel_launch(void* const* d_in, const int* in_sizes, int n_in,
                              void* d_out, int out_size) {
    const float* img = (const float*)d_in[0];
    const float* h   = (const float*)d_in[1];
    const float* wc  = (const float*)d_in[2];
    const float* bc  = (const float*)d_in[3];
    const float* whc = (const float*)d_in[4];
    const float* wci = (const float*)d_in[5];
    // d_in[6] = bci : dropped (softmax shift-invariant)
    const float* ws  = (const float*)d_in[7];
    const float* bs  = (const float*)d_in[8];
    const float* whs = (const float*)d_in[9];
    const float* wsi = (const float*)d_in[10];
    // d_in[11] = bsi : dropped (softmax shift-invariant)
    float* out = (float*)d_out;

    k0_zero<<<(B * PP + 255) / 256, 256>>>();
    k1_stats<<<(B * C) / 8, 256>>>(img);
    k2_proj<<<B, KK>>>(h, whc, whs, bc, bs);
    k3_sc<<<dim3(C / 256, B), 256>>>(wc, wci);
    k4_softmax_c<<<B, 256>>>();
    k5_xw<<<dim3(C / 128, B), 256>>>(img);
    k6_inv<<<(B * PP + 255) / 256, 256>>>();
    k7_ss<<<dim3(KK / 64, B), 256>>>(ws, wsi);
    k8_softmax_p<<<B, 256>>>();
    k9_out<<<(B * C * 49 + 255) / 256, 256>>>(out);
}

// round 4
// speedup vs baseline: 2.8981x; 2.8981x over previous
#include <cuda_runtime.h>
#include <cstdint>

#define DEV_INLINE __device__ __forceinline__

constexpr int B  = 64;
constexpr int C  = 2048;
constexpr int P  = 196;
constexpr int PP = 224;    // p padded: 4 warps * 56
constexpr int KK = 512;
constexpr int HS = 1024;

// ---- scratch ----
static __device__ float g_ic[B * C];
static __device__ float g_bcu[B * KK];
static __device__ float g_bsu[B * KK];
static __device__ float g_sc[B * C];
static __device__ float g_ac[B * C];
static __device__ float g_wst[KK * C];                 // ws rounded to tf32
static __device__ float g_xwT[(size_t)B * PP * C];     // transposed weighted features (pad rows stay 0)
static __device__ float g_ssq[B * PP];
static __device__ float g_inv[B * PP];
static __device__ float g_ss[B * P];
static __device__ float g_asp[B * P];

DEV_INLINE float tanh_fast(float x) { float y; asm("tanh.approx.f32 %0, %1;" : "=f"(y) : "f"(x)); return y; }
DEV_INLINE float to_tf32(float x)   { float y; asm("cvt.rna.tf32.f32 %0, %1;" : "=f"(y) : "f"(x)); return y; }
DEV_INLINE uint32_t smem_u32(const void* p) {
    uint32_t a;
    asm("{ .reg .u64 t; cvta.to.shared.u64 t, %1; cvt.u32.u64 %0, t; }" : "=r"(a) : "l"(p));
    return a;
}
DEV_INLINE void cp16(uint32_t dst, const void* src) {
    asm volatile("cp.async.cg.shared.global [%0], [%1], 16;" :: "r"(dst), "l"(src));
}

// ---- K0: zero accumulators ----
__global__ void k0_zero() {
    int i = blockIdx.x * 256 + threadIdx.x;
    if (i < B * PP) g_ssq[i] = 0.f;
    if (i < B * P)  g_ss[i]  = 0.f;
}

// ---- Kp: round ws to tf32 ----
__global__ void kprep(const float* __restrict__ ws) {
    int i = blockIdx.x * 256 + threadIdx.x;
    if (i >= KK * C / 4) return;
    float4 v = ((const float4*)ws)[i];
    v.x = to_tf32(v.x); v.y = to_tf32(v.y); v.z = to_tf32(v.z); v.w = to_tf32(v.w);
    ((float4*)g_wst)[i] = v;
}

// ---- K1: per-(b,c) sum & sumsq over P ----
__global__ void k1_stats(const float* __restrict__ x) {
    int warp = (blockIdx.x * blockDim.x + threadIdx.x) >> 5;
    int lane = threadIdx.x & 31;
    if (warp >= B * C) return;
    const float4* row = (const float4*)(x + (size_t)warp * P);
    float s = 0.f, sq = 0.f;
    for (int v = lane; v < 49; v += 32) {
        float4 f = row[v];
        s  += f.x + f.y + f.z + f.w;
        sq += f.x * f.x + f.y * f.y + f.z * f.z + f.w * f.w;
    }
    #pragma unroll
    for (int o = 16; o; o >>= 1) {
        s  += __shfl_down_sync(0xffffffffu, s,  o);
        sq += __shfl_down_sync(0xffffffffu, sq, o);
    }
    if (lane == 0) g_ic[warp] = s / (196.f * fmaxf(sqrtf(sq), 1e-12f));
}

// ---- K2: bcu = whc@h + bc, bsu = whs@h + bs ----
__global__ void k2_proj(const float* __restrict__ h, const float* __restrict__ whc,
                        const float* __restrict__ whs, const float* __restrict__ bc,
                        const float* __restrict__ bs) {
    int b = blockIdx.x, j = threadIdx.x;
    __shared__ float4 hsm[HS / 4];
    for (int i = threadIdx.x; i < HS / 4; i += KK) hsm[i] = ((const float4*)(h + (size_t)b * HS))[i];
    __syncthreads();
    const float4* rc = (const float4*)(whc + (size_t)j * HS);
    const float4* rs = (const float4*)(whs + (size_t)j * HS);
    float a = 0.f, d = 0.f;
    #pragma unroll 4
    for (int i = 0; i < HS / 4; i++) {
        float4 hv = hsm[i], c4 = rc[i], s4 = rs[i];
        a = fmaf(c4.x, hv.x, fmaf(c4.y, hv.y, fmaf(c4.z, hv.z, fmaf(c4.w, hv.w, a))));
        d = fmaf(s4.x, hv.x, fmaf(s4.y, hv.y, fmaf(s4.z, hv.z, fmaf(s4.w, hv.w, d))));
    }
    g_bcu[b * KK + j] = a + bc[j];
    g_bsu[b * KK + j] = d + bs[j];
}

// ---- K3: channel logits ----
__global__ void k3_sc(const float* __restrict__ wc, const float* __restrict__ wci) {
    int b = blockIdx.y;
    int c = blockIdx.x * 256 + threadIdx.x;
    __shared__ float swc[KK], swi[KK], sbu[KK];
    for (int i = threadIdx.x; i < KK; i += 256) {
        swc[i] = wc[i]; swi[i] = wci[i]; sbu[i] = g_bcu[b * KK + i];
    }
    __syncthreads();
    float icv = g_ic[b * C + c], acc = 0.f;
    #pragma unroll 8
    for (int j = 0; j < KK; j++)
        acc = fmaf(swi[j], tanh_fast(fmaf(swc[j], icv, sbu[j])), acc);
    g_sc[b * C + c] = acc;
}

// ---- K4: softmax over C ----
__global__ void k4_softmax_c() {
    int b = blockIdx.x, t = threadIdx.x;
    __shared__ float red[256];
    float vals[8]; float m = -1e30f;
    #pragma unroll
    for (int i = 0; i < 8; i++) { vals[i] = g_sc[b * C + t + 256 * i]; m = fmaxf(m, vals[i]); }
    red[t] = m; __syncthreads();
    for (int o = 128; o; o >>= 1) { if (t < o) red[t] = fmaxf(red[t], red[t + o]); __syncthreads(); }
    m = red[0]; __syncthreads();
    float s = 0.f;
    #pragma unroll
    for (int i = 0; i < 8; i++) { vals[i] = __expf(vals[i] - m); s += vals[i]; }
    red[t] = s; __syncthreads();
    for (int o = 128; o; o >>= 1) { if (t < o) red[t] += red[t + o]; __syncthreads(); }
    float inv = 1.f / red[0];
    #pragma unroll
    for (int i = 0; i < 8; i++) g_ac[b * C + t + 256 * i] = vals[i] * inv;
}

// ---- K5: xwT[b][p][c] = tf32(x*ac); accumulate ssq per (b,p) ----
__global__ void __launch_bounds__(256) k5_xwT(const float* __restrict__ x) {
    int b = blockIdx.y, c0 = blockIdx.x * 32;
    __shared__ float t[32][201];
    int tid = threadIdx.x;
    for (int idx = tid; idx < 32 * 49; idx += 256) {
        int cc = idx / 49, q = idx % 49;
        float a = g_ac[b * C + c0 + cc];
        float4 v = ((const float4*)(x + ((size_t)b * C + c0 + cc) * P))[q];
        t[cc][4 * q + 0] = to_tf32(v.x * a);
        t[cc][4 * q + 1] = to_tf32(v.y * a);
        t[cc][4 * q + 2] = to_tf32(v.z * a);
        t[cc][4 * q + 3] = to_tf32(v.w * a);
    }
    __syncthreads();
    int lane = tid & 31, w = tid >> 5;
    for (int p = w; p < P; p += 8) {
        float v = t[lane][p];
        g_xwT[((size_t)b * PP + p) * C + c0 + lane] = v;
        float s = v * v;
        #pragma unroll
        for (int o = 16; o; o >>= 1) s += __shfl_down_sync(0xffffffffu, s, o);
        if (lane == 0) atomicAdd(&g_ssq[b * PP + p], s);
    }
}

// ---- K6: inv spatial norms ----
__global__ void k6_inv() {
    int i = blockIdx.x * 256 + threadIdx.x;
    if (i < B * PP) g_inv[i] = 1.f / fmaxf(sqrtf(g_ssq[i]), 1e-12f);
}

// ================= K7: mma.sync tf32 GEMM + fused epilogue =================
// grid = (quarter=4, b=64). CTA: M=128 (j), N=224 (p), K=2048 (c).
// smem: stage s: A[128][36] @ s*50688, B[224][36] @ s*50688+18432 ; sinv @101376 ; ssacc @102272
constexpr int STG   = 50688;
constexpr int A_SZ  = 18432;
constexpr int SMEM_K7 = 2 * STG + 224 * 4 * 2;  // 103168

DEV_INLINE void mma8(float* c, const uint32_t* a, const uint32_t* bf) {
    asm volatile(
        "mma.sync.aligned.m16n8k8.row.col.f32.tf32.tf32.f32 "
        "{%0,%1,%2,%3}, {%4,%5,%6,%7}, {%8,%9}, {%0,%1,%2,%3};"
        : "+f"(c[0]), "+f"(c[1]), "+f"(c[2]), "+f"(c[3])
        : "r"(a[0]), "r"(a[1]), "r"(a[2]), "r"(a[3]), "r"(bf[0]), "r"(bf[1]));
}

__global__ void __launch_bounds__(256, 1) k7_mma(const float* __restrict__ wsi) {
    extern __shared__ __align__(16) char sm[];
    const int tid = threadIdx.x;
    const int jbase = blockIdx.x * 128;
    const int b = blockIdx.y;
    const uint32_t sb = smem_u32(sm);

    const int wid = tid >> 5, lane = tid & 31;
    const int g = lane >> 2, t4 = lane & 3;
    const int m0 = (wid & 1) * 64;       // warp M offset (0/64)
    const int n0 = (wid >> 1) * 56;      // warp N offset (0..168)

    const size_t bbase = (size_t)b * PP;

    // cp.async loader for chunk ch into buffer buf
    auto load_chunk = [&](int ch, int buf) {
        uint32_t abase = sb + buf * STG;
        uint32_t bbs   = abase + A_SZ;
        const float* asrc = g_wst + ch * 32;
        const float* bsrc = g_xwT + bbase * 2048 + ch * 32;
        int idx = tid;
        #pragma unroll
        for (int r = 0; r < 4; r++, idx += 256) {         // A: 128 rows x 8 q
            int row = idx >> 3, q = idx & 7;
            cp16(abase + row * 144 + q * 16, asrc + (size_t)(jbase + row) * 2048 + q * 4);
        }
        idx = tid;
        #pragma unroll
        for (int r = 0; r < 7; r++, idx += 256) {         // B: 224 rows x 8 q
            int row = idx >> 3, q = idx & 7;
            cp16(bbs + row * 144 + q * 16, bsrc + (size_t)row * 2048 + q * 4);
        }
        asm volatile("cp.async.commit_group;");
    };

    float acc[4][7][4];
    #pragma unroll
    for (int mf = 0; mf < 4; mf++)
        #pragma unroll
        for (int nf = 0; nf < 7; nf++)
            #pragma unroll
            for (int i = 0; i < 4; i++) acc[mf][nf][i] = 0.f;

    load_chunk(0, 0);

    for (int ch = 0; ch < 64; ch++) {
        int buf = ch & 1;
        if (ch + 1 < 64) {
            load_chunk(ch + 1, buf ^ 1);
            asm volatile("cp.async.wait_group %0;" :: "n"(1));
        } else {
            asm volatile("cp.async.wait_group %0;" :: "n"(0));
        }
        __syncthreads();

        const float* sA = (const float*)(sm + buf * STG);
        const float* sB = (const float*)(sm + buf * STG + A_SZ);
        const float* aB = sA + (m0 + g) * 36 + t4;
        const float* bB = sB + (n0 + g) * 36 + t4;

        #pragma unroll
        for (int kk = 0; kk < 32; kk += 8) {
            uint32_t a[4][4];
            #pragma unroll
            for (int mf = 0; mf < 4; mf++) {
                a[mf][0] = __float_as_uint(aB[(mf * 16    ) * 36 + kk    ]);
                a[mf][1] = __float_as_uint(aB[(mf * 16 + 8) * 36 + kk    ]);
                a[mf][2] = __float_as_uint(aB[(mf * 16    ) * 36 + kk + 4]);
                a[mf][3] = __float_as_uint(aB[(mf * 16 + 8) * 36 + kk + 4]);
            }
            uint32_t bf[7][2];
            #pragma unroll
            for (int nf = 0; nf < 7; nf++) {
                bf[nf][0] = __float_as_uint(bB[nf * 8 * 36 + kk    ]);
                bf[nf][1] = __float_as_uint(bB[nf * 8 * 36 + kk + 4]);
            }
            #pragma unroll
            for (int mf = 0; mf < 4; mf++)
                #pragma unroll
                for (int nf = 0; nf < 7; nf++)
                    mma8(acc[mf][nf], a[mf], bf[nf]);
        }
        __syncthreads();
    }

    // ---- fused epilogue ----
    float* sinv  = (float*)(sm + 2 * STG);
    float* ssacc = sinv + 224;
    for (int i = tid; i < 224; i += 256) { sinv[i] = g_inv[bbase + i]; ssacc[i] = 0.f; }
    __syncthreads();

    float invp[14];
    #pragma unroll
    for (int nf = 0; nf < 7; nf++) {
        invp[nf * 2 + 0] = sinv[n0 + nf * 8 + 2 * t4 + 0];
        invp[nf * 2 + 1] = sinv[n0 + nf * 8 + 2 * t4 + 1];
    }
    float psum[14];
    #pragma unroll
    for (int i = 0; i < 14; i++) psum[i] = 0.f;

    #pragma unroll
    for (int mf = 0; mf < 4; mf++) {
        #pragma unroll
        for (int rr = 0; rr < 2; rr++) {
            int j = jbase + m0 + mf * 16 + rr * 8 + g;
            float bj = g_bsu[b * KK + j];
            float wj = wsi[j];
            #pragma unroll
            for (int nf = 0; nf < 7; nf++) {
                #pragma unroll
                for (int cc = 0; cc < 2; cc++) {
                    float d = acc[mf][nf][rr * 2 + cc];
                    psum[nf * 2 + cc] = fmaf(wj, tanh_fast(fmaf(d, invp[nf * 2 + cc], bj)),
                                             psum[nf * 2 + cc]);
                }
            }
        }
    }
    #pragma unroll
    for (int nf = 0; nf < 7; nf++)
        #pragma unroll
        for (int cc = 0; cc < 2; cc++) {
            int p = n0 + nf * 8 + 2 * t4 + cc;
            if (p < P) atomicAdd(&ssacc[p], psum[nf * 2 + cc]);
        }
    __syncthreads();
    if (tid < P) atomicAdd(&g_ss[b * P + tid], ssacc[tid]);
}

// ---- K8: softmax over P ----
__global__ void k8_softmax_p() {
    int b = blockIdx.x, t = threadIdx.x;
    __shared__ float red[256];
    float v = (t < P) ? g_ss[b * P + t] : -1e30f;
    red[t] = v; __syncthreads();
    for (int o = 128; o; o >>= 1) { if (t < o) red[t] = fmaxf(red[t], red[t + o]); __syncthreads(); }
    float m = red[0]; __syncthreads();
    float e = (t < P) ? __expf(v - m) : 0.f;
    red[t] = e; __syncthreads();
    for (int o = 128; o; o >>= 1) { if (t < o) red[t] += red[t + o]; __syncthreads(); }
    if (t < P) g_asp[b * P + t] = e / red[0];
}

// ---- K9: out = img * ac * asp ----
__global__ void k9_out(const float* __restrict__ x, float* __restrict__ out) {
    int idx = blockIdx.x * 256 + threadIdx.x;
    if (idx >= B * C * 49) return;
    int q = idx % 49;
    int bc = idx / 49;
    int b = bc >> 11;
    float a = g_ac[bc];
    float4 v = ((const float4*)x)[idx];
    float4 s = ((const float4*)g_asp)[b * 49 + q];
    float4 o;
    o.x = v.x * a * s.x; o.y = v.y * a * s.y; o.z = v.z * a * s.z; o.w = v.w * a * s.w;
    ((float4*)out)[idx] = o;
}

extern "C" void kernel_launch(void* const* d_in, const int* in_sizes, int n_in,
                              void* d_out, int out_size) {
    const float* img = (const float*)d_in[0];
    const float* h   = (const float*)d_in[1];
    const float* wc  = (const float*)d_in[2];
    const float* bc  = (const float*)d_in[3];
    const float* whc = (const float*)d_in[4];
    const float* wci = (const float*)d_in[5];
    const float* ws  = (const float*)d_in[7];
    const float* bs  = (const float*)d_in[8];
    const float* whs = (const float*)d_in[9];
    const float* wsi = (const float*)d_in[10];
    float* out = (float*)d_out;

    cudaFuncSetAttribute(k7_mma, cudaFuncAttributeMaxDynamicSharedMemorySize, SMEM_K7);

    kprep<<<(KK * C / 4 + 255) / 256, 256>>>(ws);
    k0_zero<<<(B * PP + 255) / 256, 256>>>();
    k1_stats<<<(B * C) / 8, 256>>>(img);
    k2_proj<<<B, KK>>>(h, whc, whs, bc, bs);
    k3_sc<<<dim3(C / 256, B), 256>>>(wc, wci);
    k4_softmax_c<<<B, 256>>>();
    k5_xwT<<<dim3(C / 32, B), 256>>>(img);
    k6_inv<<<(B * PP + 255) / 256, 256>>>();
    k7_mma<<<dim3(4, B), 256, SMEM_K7>>>(wsi);
    k8_softmax_p<<<B, 256>>>();
    k9_out<<<(B * C * 49 + 255) / 256, 256>>>(img, out);
}

// round 5
// speedup vs baseline: 3.7318x; 1.2877x over previous
#include <cuda_runtime.h>
#include <cstdint>

#define DEV_INLINE __device__ __forceinline__

constexpr int B  = 64;
constexpr int C  = 2048;
constexpr int P  = 196;
constexpr int PP = 224;    // p padded: 4 warps * 56
constexpr int KK = 512;
constexpr int HS = 1024;

// ---- scratch ----
static __device__ float g_ic[B * C];
static __device__ float g_bcu[B * KK];
static __device__ float g_bsu[B * KK];
static __device__ float g_sc[B * C];
static __device__ float g_ac[B * C];
static __device__ float g_wst[KK * C];                 // ws rounded to tf32
static __device__ float g_xwT[(size_t)B * PP * C];     // transposed weighted features (pad rows stay 0)
static __device__ float g_ssq[B * PP];
static __device__ float g_inv[B * PP];
static __device__ float g_ss[B * P];
static __device__ float g_asp[B * P];

DEV_INLINE float tanh_fast(float x) { float y; asm("tanh.approx.f32 %0, %1;" : "=f"(y) : "f"(x)); return y; }
DEV_INLINE float to_tf32(float x)   { float y; asm("cvt.rna.tf32.f32 %0, %1;" : "=f"(y) : "f"(x)); return y; }
DEV_INLINE uint32_t smem_u32(const void* p) {
    uint32_t a;
    asm("{ .reg .u64 t; cvta.to.shared.u64 t, %1; cvt.u32.u64 %0, t; }" : "=r"(a) : "l"(p));
    return a;
}
DEV_INLINE void cp16(uint32_t dst, const void* src) {
    asm volatile("cp.async.cg.shared.global [%0], [%1], 16;" :: "r"(dst), "l"(src));
}

// ---- K0: zero accumulators ----
__global__ void k0_zero() {
    int i = blockIdx.x * 256 + threadIdx.x;
    if (i < B * PP) g_ssq[i] = 0.f;
    if (i < B * P)  g_ss[i]  = 0.f;
    if (i < B * KK) { g_bcu[i] = 0.f; g_bsu[i] = 0.f; }
}

// ---- Kp: round ws to tf32 ----
__global__ void kprep(const float* __restrict__ ws) {
    int i = blockIdx.x * 256 + threadIdx.x;
    if (i >= KK * C / 4) return;
    float4 v = ((const float4*)ws)[i];
    v.x = to_tf32(v.x); v.y = to_tf32(v.y); v.z = to_tf32(v.z); v.w = to_tf32(v.w);
    ((float4*)g_wst)[i] = v;
}

// ---- K1: per-(b,c) sum & sumsq over P ----
__global__ void k1_stats(const float* __restrict__ x) {
    int warp = (blockIdx.x * blockDim.x + threadIdx.x) >> 5;
    int lane = threadIdx.x & 31;
    if (warp >= B * C) return;
    const float4* row = (const float4*)(x + (size_t)warp * P);
    float s = 0.f, sq = 0.f;
    for (int v = lane; v < 49; v += 32) {
        float4 f = row[v];
        s  += f.x + f.y + f.z + f.w;
        sq += f.x * f.x + f.y * f.y + f.z * f.z + f.w * f.w;
    }
    #pragma unroll
    for (int o = 16; o; o >>= 1) {
        s  += __shfl_down_sync(0xffffffffu, s,  o);
        sq += __shfl_down_sync(0xffffffffu, sq, o);
    }
    if (lane == 0) g_ic[warp] = s / (196.f * fmaxf(sqrtf(sq), 1e-12f));
}

// ---- K2: split-K tiled GEMM: bcu += whc@h, bsu += whs@h ----
// grid (16 j-tiles, 16 k-splits, 2 mats), block 256. Tile: 32 j x 64 b x 64 k.
__global__ void __launch_bounds__(256) k2_gemm(const float* __restrict__ h,
                                               const float* __restrict__ whc,
                                               const float* __restrict__ whs) {
    int jt = blockIdx.x, ks = blockIdx.y, mat = blockIdx.z;
    const float4* w4 = (const float4*)(mat ? whs : whc);
    const float4* h4 = (const float4*)h;
    float* outp = mat ? g_bsu : g_bcu;
    int j0 = jt * 32, kq0 = ks * 16;   // k offset in float4 units (64 floats)
    __shared__ float4 sh[64][17];
    __shared__ float4 sw[32][17];
    int tid = threadIdx.x;
    #pragma unroll
    for (int r = 0; r < 4; r++) {
        int idx = tid + 256 * r;
        sh[idx >> 4][idx & 15] = h4[(size_t)(idx >> 4) * 256 + kq0 + (idx & 15)];
    }
    #pragma unroll
    for (int r = 0; r < 2; r++) {
        int idx = tid + 256 * r;
        sw[idx >> 4][idx & 15] = w4[(size_t)(j0 + (idx >> 4)) * 256 + kq0 + (idx & 15)];
    }
    __syncthreads();
    int bq = tid & 15;   // b = 4*bq + bb
    int jq = tid >> 4;   // j = j0 + 2*jq + jj
    float acc[2][4] = {{0.f,0.f,0.f,0.f},{0.f,0.f,0.f,0.f}};
    #pragma unroll
    for (int q = 0; q < 16; q++) {
        float4 w0 = sw[2 * jq][q], w1 = sw[2 * jq + 1][q];
        #pragma unroll
        for (int bb = 0; bb < 4; bb++) {
            float4 hv = sh[4 * bq + bb][q];
            acc[0][bb] = fmaf(w0.x, hv.x, fmaf(w0.y, hv.y, fmaf(w0.z, hv.z, fmaf(w0.w, hv.w, acc[0][bb]))));
            acc[1][bb] = fmaf(w1.x, hv.x, fmaf(w1.y, hv.y, fmaf(w1.z, hv.z, fmaf(w1.w, hv.w, acc[1][bb]))));
        }
    }
    #pragma unroll
    for (int jj = 0; jj < 2; jj++)
        #pragma unroll
        for (int bb = 0; bb < 4; bb++)
            atomicAdd(&outp[(4 * bq + bb) * KK + j0 + 2 * jq + jj], acc[jj][bb]);
}

// ---- K3: channel logits (bc folded here) ----
__global__ void k3_sc(const float* __restrict__ wc, const float* __restrict__ wci,
                      const float* __restrict__ bc) {
    int b = blockIdx.y;
    int c = blockIdx.x * 256 + threadIdx.x;
    __shared__ float swc[KK], swi[KK], sbu[KK];
    for (int i = threadIdx.x; i < KK; i += 256) {
        swc[i] = wc[i]; swi[i] = wci[i]; sbu[i] = g_bcu[b * KK + i] + bc[i];
    }
    __syncthreads();
    float icv = g_ic[b * C + c], acc = 0.f;
    #pragma unroll 8
    for (int j = 0; j < KK; j++)
        acc = fmaf(swi[j], tanh_fast(fmaf(swc[j], icv, sbu[j])), acc);
    g_sc[b * C + c] = acc;
}

// ---- K4: softmax over C ----
__global__ void k4_softmax_c() {
    int b = blockIdx.x, t = threadIdx.x;
    __shared__ float red[256];
    float vals[8]; float m = -1e30f;
    #pragma unroll
    for (int i = 0; i < 8; i++) { vals[i] = g_sc[b * C + t + 256 * i]; m = fmaxf(m, vals[i]); }
    red[t] = m; __syncthreads();
    for (int o = 128; o; o >>= 1) { if (t < o) red[t] = fmaxf(red[t], red[t + o]); __syncthreads(); }
    m = red[0]; __syncthreads();
    float s = 0.f;
    #pragma unroll
    for (int i = 0; i < 8; i++) { vals[i] = __expf(vals[i] - m); s += vals[i]; }
    red[t] = s; __syncthreads();
    for (int o = 128; o; o >>= 1) { if (t < o) red[t] += red[t + o]; __syncthreads(); }
    float inv = 1.f / red[0];
    #pragma unroll
    for (int i = 0; i < 8; i++) g_ac[b * C + t + 256 * i] = vals[i] * inv;
}

// ---- K5: xwT[b][p][c] = tf32(x*ac); accumulate ssq per (b,p) ----
__global__ void __launch_bounds__(256) k5_xwT(const float* __restrict__ x) {
    int b = blockIdx.y, c0 = blockIdx.x * 32;
    __shared__ float t[32][201];
    int tid = threadIdx.x;
    for (int idx = tid; idx < 32 * 49; idx += 256) {
        int cc = idx / 49, q = idx % 49;
        float a = g_ac[b * C + c0 + cc];
        float4 v = ((const float4*)(x + ((size_t)b * C + c0 + cc) * P))[q];
        t[cc][4 * q + 0] = to_tf32(v.x * a);
        t[cc][4 * q + 1] = to_tf32(v.y * a);
        t[cc][4 * q + 2] = to_tf32(v.z * a);
        t[cc][4 * q + 3] = to_tf32(v.w * a);
    }
    __syncthreads();
    int lane = tid & 31, w = tid >> 5;
    for (int p = w; p < P; p += 8) {
        float v = t[lane][p];
        g_xwT[((size_t)b * PP + p) * C + c0 + lane] = v;
        float s = v * v;
        #pragma unroll
        for (int o = 16; o; o >>= 1) s += __shfl_down_sync(0xffffffffu, s, o);
        if (lane == 0) atomicAdd(&g_ssq[b * PP + p], s);
    }
}

// ---- K6: inv spatial norms ----
__global__ void k6_inv() {
    int i = blockIdx.x * 256 + threadIdx.x;
    if (i < B * PP) g_inv[i] = 1.f / fmaxf(sqrtf(g_ssq[i]), 1e-12f);
}

// ================= K7: mma.sync tf32 GEMM + fused epilogue =================
constexpr int STG   = 50688;
constexpr int A_SZ  = 18432;
constexpr int SMEM_K7 = 2 * STG + 224 * 4 * 2;  // 103168

DEV_INLINE void mma8(float* c, const uint32_t* a, const uint32_t* bf) {
    asm volatile(
        "mma.sync.aligned.m16n8k8.row.col.f32.tf32.tf32.f32 "
        "{%0,%1,%2,%3}, {%4,%5,%6,%7}, {%8,%9}, {%0,%1,%2,%3};"
        : "+f"(c[0]), "+f"(c[1]), "+f"(c[2]), "+f"(c[3])
        : "r"(a[0]), "r"(a[1]), "r"(a[2]), "r"(a[3]), "r"(bf[0]), "r"(bf[1]));
}

__global__ void __launch_bounds__(256, 1) k7_mma(const float* __restrict__ wsi,
                                                 const float* __restrict__ bs) {
    extern __shared__ __align__(16) char sm[];
    const int tid = threadIdx.x;
    const int jbase = blockIdx.x * 128;
    const int b = blockIdx.y;
    const uint32_t sb = smem_u32(sm);

    const int wid = tid >> 5, lane = tid & 31;
    const int g = lane >> 2, t4 = lane & 3;
    const int m0 = (wid & 1) * 64;
    const int n0 = (wid >> 1) * 56;

    const size_t bbase = (size_t)b * PP;

    auto load_chunk = [&](int ch, int buf) {
        uint32_t abase = sb + buf * STG;
        uint32_t bbs   = abase + A_SZ;
        const float* asrc = g_wst + ch * 32;
        const float* bsrc = g_xwT + bbase * 2048 + ch * 32;
        int idx = tid;
        #pragma unroll
        for (int r = 0; r < 4; r++, idx += 256) {
            int row = idx >> 3, q = idx & 7;
            cp16(abase + row * 144 + q * 16, asrc + (size_t)(jbase + row) * 2048 + q * 4);
        }
        idx = tid;
        #pragma unroll
        for (int r = 0; r < 7; r++, idx += 256) {
            int row = idx >> 3, q = idx & 7;
            cp16(bbs + row * 144 + q * 16, bsrc + (size_t)row * 2048 + q * 4);
        }
        asm volatile("cp.async.commit_group;");
    };

    float acc[4][7][4];
    #pragma unroll
    for (int mf = 0; mf < 4; mf++)
        #pragma unroll
        for (int nf = 0; nf < 7; nf++)
            #pragma unroll
            for (int i = 0; i < 4; i++) acc[mf][nf][i] = 0.f;

    load_chunk(0, 0);

    for (int ch = 0; ch < 64; ch++) {
        int buf = ch & 1;
        if (ch + 1 < 64) {
            load_chunk(ch + 1, buf ^ 1);
            asm volatile("cp.async.wait_group %0;" :: "n"(1));
        } else {
            asm volatile("cp.async.wait_group %0;" :: "n"(0));
        }
        __syncthreads();

        const float* sA = (const float*)(sm + buf * STG);
        const float* sB = (const float*)(sm + buf * STG + A_SZ);
        const float* aB = sA + (m0 + g) * 36 + t4;
        const float* bB = sB + (n0 + g) * 36 + t4;

        #pragma unroll
        for (int kk = 0; kk < 32; kk += 8) {
            uint32_t a[4][4];
            #pragma unroll
            for (int mf = 0; mf < 4; mf++) {
                a[mf][0] = __float_as_uint(aB[(mf * 16    ) * 36 + kk    ]);
                a[mf][1] = __float_as_uint(aB[(mf * 16 + 8) * 36 + kk    ]);
                a[mf][2] = __float_as_uint(aB[(mf * 16    ) * 36 + kk + 4]);
                a[mf][3] = __float_as_uint(aB[(mf * 16 + 8) * 36 + kk + 4]);
            }
            uint32_t bf[7][2];
            #pragma unroll
            for (int nf = 0; nf < 7; nf++) {
                bf[nf][0] = __float_as_uint(bB[nf * 8 * 36 + kk    ]);
                bf[nf][1] = __float_as_uint(bB[nf * 8 * 36 + kk + 4]);
            }
            #pragma unroll
            for (int mf = 0; mf < 4; mf++)
                #pragma unroll
                for (int nf = 0; nf < 7; nf++)
                    mma8(acc[mf][nf], a[mf], bf[nf]);
        }
        __syncthreads();
    }

    // ---- fused epilogue ----
    float* sinv  = (float*)(sm + 2 * STG);
    float* ssacc = sinv + 224;
    for (int i = tid; i < 224; i += 256) { sinv[i] = g_inv[bbase + i]; ssacc[i] = 0.f; }
    __syncthreads();

    float invp[14];
    #pragma unroll
    for (int nf = 0; nf < 7; nf++) {
        invp[nf * 2 + 0] = sinv[n0 + nf * 8 + 2 * t4 + 0];
        invp[nf * 2 + 1] = sinv[n0 + nf * 8 + 2 * t4 + 1];
    }
    float psum[14];
    #pragma unroll
    for (int i = 0; i < 14; i++) psum[i] = 0.f;

    #pragma unroll
    for (int mf = 0; mf < 4; mf++) {
        #pragma unroll
        for (int rr = 0; rr < 2; rr++) {
            int j = jbase + m0 + mf * 16 + rr * 8 + g;
            float bj = g_bsu[b * KK + j] + bs[j];
            float wj = wsi[j];
            #pragma unroll
            for (int nf = 0; nf < 7; nf++) {
                #pragma unroll
                for (int cc = 0; cc < 2; cc++) {
                    float d = acc[mf][nf][rr * 2 + cc];
                    psum[nf * 2 + cc] = fmaf(wj, tanh_fast(fmaf(d, invp[nf * 2 + cc], bj)),
                                             psum[nf * 2 + cc]);
                }
            }
        }
    }
    #pragma unroll
    for (int nf = 0; nf < 7; nf++)
        #pragma unroll
        for (int cc = 0; cc < 2; cc++) {
            int p = n0 + nf * 8 + 2 * t4 + cc;
            if (p < P) atomicAdd(&ssacc[p], psum[nf * 2 + cc]);
        }
    __syncthreads();
    if (tid < P) atomicAdd(&g_ss[b * P + tid], ssacc[tid]);
}

// ---- K8: softmax over P ----
__global__ void k8_softmax_p() {
    int b = blockIdx.x, t = threadIdx.x;
    __shared__ float red[256];
    float v = (t < P) ? g_ss[b * P + t] : -1e30f;
    red[t] = v; __syncthreads();
    for (int o = 128; o; o >>= 1) { if (t < o) red[t] = fmaxf(red[t], red[t + o]); __syncthreads(); }
    float m = red[0]; __syncthreads();
    float e = (t < P) ? __expf(v - m) : 0.f;
    red[t] = e; __syncthreads();
    for (int o = 128; o; o >>= 1) { if (t < o) red[t] += red[t + o]; __syncthreads(); }
    if (t < P) g_asp[b * P + t] = e / red[0];
}

// ---- K9: out = img * ac * asp ----
__global__ void k9_out(const float* __restrict__ x, float* __restrict__ out) {
    int idx = blockIdx.x * 256 + threadIdx.x;
    if (idx >= B * C * 49) return;
    int q = idx % 49;
    int bc = idx / 49;
    int b = bc >> 11;
    float a = g_ac[bc];
    float4 v = ((const float4*)x)[idx];
    float4 s = ((const float4*)g_asp)[b * 49 + q];
    float4 o;
    o.x = v.x * a * s.x; o.y = v.y * a * s.y; o.z = v.z * a * s.z; o.w = v.w * a * s.w;
    ((float4*)out)[idx] = o;
}

extern "C" void kernel_launch(void* const* d_in, const int* in_sizes, int n_in,
                              void* d_out, int out_size) {
    const float* img = (const float*)d_in[0];
    const float* h   = (const float*)d_in[1];
    const float* wc  = (const float*)d_in[2];
    const float* bc  = (const float*)d_in[3];
    const float* whc = (const float*)d_in[4];
    const float* wci = (const float*)d_in[5];
    const float* ws  = (const float*)d_in[7];
    const float* bs  = (const float*)d_in[8];
    const float* whs = (const float*)d_in[9];
    const float* wsi = (const float*)d_in[10];
    float* out = (float*)d_out;

    cudaFuncSetAttribute(k7_mma, cudaFuncAttributeMaxDynamicSharedMemorySize, SMEM_K7);

    k0_zero<<<(B * KK + 255) / 256, 256>>>();
    kprep<<<(KK * C / 4 + 255) / 256, 256>>>(ws);
    k1_stats<<<(B * C) / 8, 256>>>(img);
    k2_gemm<<<dim3(16, 16, 2), 256>>>(h, whc, whs);
    k3_sc<<<dim3(C / 256, B), 256>>>(wc, wci, bc);
    k4_softmax_c<<<B, 256>>>();
    k5_xwT<<<dim3(C / 32, B), 256>>>(img);
    k6_inv<<<(B * PP + 255) / 256, 256>>>();
    k7_mma<<<dim3(4, B), 256, SMEM_K7>>>(wsi, bs);
    k8_softmax_p<<<B, 256>>>();
    k9_out<<<(B * C * 49 + 255) / 256, 256>>>(img, out);
}